// round 1
// baseline (speedup 1.0000x reference)
#include <cuda_runtime.h>
#include <math.h>

#define BATCH 4
#define CH    256
#define HWN   4096      // H*W
#define GROUPS 32
#define CPG    8        // CH/GROUPS
#define NHEADS 4
#define HD     64
#define EPSV   1e-5f

// ---- scratch (allocation-free: __device__ globals) ----
__device__ float g_xn [BATCH*CH*HWN];
__device__ float g_kvn[BATCH*CH*HWN];
__device__ float g_q  [BATCH*CH*HWN];
__device__ float g_k  [BATCH*CH*HWN];
__device__ float g_v  [BATCH*CH*HWN];
__device__ float g_ao [BATCH*CH*HWN];

// =====================================================================
// GroupNorm: one block per (b, group, which-tensor). 256 threads.
// group = 8 channels * 4096 = 32768 floats = 8192 float4.
// =====================================================================
__global__ void gn_kernel(const float* __restrict__ x,
                          const float* __restrict__ cond,
                          const float* __restrict__ gqw, const float* __restrict__ gqb,
                          const float* __restrict__ gkw, const float* __restrict__ gkb)
{
    const int kv = blockIdx.y;
    const float* in  = kv ? cond : x;
    float*       out = kv ? g_kvn : g_xn;
    const float* gw  = kv ? gkw : gqw;
    const float* gb  = kv ? gkb : gqb;

    const int b = blockIdx.x / GROUPS;
    const int g = blockIdx.x % GROUPS;
    const size_t base_off = ((size_t)b*CH + (size_t)g*CPG) * HWN;
    const float4* in4  = (const float4*)(in  + base_off);
    float4*       out4 = (float4*)(out + base_off);

    float s = 0.f, ss = 0.f;
    for (int i = threadIdx.x; i < (CPG*HWN)/4; i += 256) {
        float4 v = in4[i];
        s  += v.x + v.y + v.z + v.w;
        ss += v.x*v.x + v.y*v.y + v.z*v.z + v.w*v.w;
    }
    // block reduce
    #pragma unroll
    for (int off = 16; off; off >>= 1) {
        s  += __shfl_xor_sync(0xffffffffu, s,  off);
        ss += __shfl_xor_sync(0xffffffffu, ss, off);
    }
    __shared__ float sm_s[8], sm_ss[8];
    if ((threadIdx.x & 31) == 0) { sm_s[threadIdx.x>>5] = s; sm_ss[threadIdx.x>>5] = ss; }
    __syncthreads();
    s = 0.f; ss = 0.f;
    #pragma unroll
    for (int w = 0; w < 8; w++) { s += sm_s[w]; ss += sm_ss[w]; }

    const float inv_n = 1.f / (float)(CPG*HWN);
    const float mean  = s * inv_n;
    const float var   = ss * inv_n - mean*mean;
    const float rstd  = rsqrtf(var + EPSV);

    for (int i = threadIdx.x; i < (CPG*HWN)/4; i += 256) {
        int ch = i >> 10;                 // i / (HWN/4)
        float gwv = gw[g*CPG + ch];
        float gbv = gb[g*CPG + ch];
        float4 v = in4[i];
        float4 o;
        o.x = (v.x - mean)*rstd*gwv + gbv;
        o.y = (v.y - mean)*rstd*gwv + gbv;
        o.z = (v.z - mean)*rstd*gwv + gbv;
        o.w = (v.w - mean)*rstd*gwv + gbv;
        out4[i] = o;
    }
}

// =====================================================================
// 1x1-conv GEMM: Y[b][o][n] = sum_c W[o][c] X[b][c][n] + bias[o] (+res)
// M=256 (o), K=256 (c), N=4096 (n). Tiles 64x64, BK=16, 256 thr, 4x4 micro.
// =====================================================================
__global__ void gemm_kernel(const float* __restrict__ W,
                            const float* __restrict__ X,
                            const float* __restrict__ bias,
                            const float* __restrict__ res,   // may be null
                            float* __restrict__ Y)
{
    const int b  = blockIdx.z;
    const int m0 = blockIdx.y * 64;
    const int n0 = blockIdx.x * 64;
    const float* Xb = X + (size_t)b*CH*HWN;

    __shared__ float Wts[16][68];   // [k][m], padded
    __shared__ float Xs [16][64];   // [k][n]

    const int t  = threadIdx.x;
    const int tx = t & 15, ty = t >> 4;
    const int wr = t >> 2, wc4 = (t & 3) * 4;   // W tile load
    const int xr = t >> 4, xc4 = (t & 15) * 4;  // X tile load

    float acc[4][4] = {};

    for (int k0 = 0; k0 < CH; k0 += 16) {
        float4 wv = *(const float4*)&W[(size_t)(m0+wr)*CH + k0 + wc4];
        Wts[wc4+0][wr] = wv.x;
        Wts[wc4+1][wr] = wv.y;
        Wts[wc4+2][wr] = wv.z;
        Wts[wc4+3][wr] = wv.w;
        *(float4*)&Xs[xr][xc4] =
            *(const float4*)&Xb[(size_t)(k0+xr)*HWN + n0 + xc4];
        __syncthreads();
        #pragma unroll
        for (int kk = 0; kk < 16; kk++) {
            float4 a  = *(const float4*)&Wts[kk][ty*4];
            float4 bb = *(const float4*)&Xs[kk][tx*4];
            float av[4] = {a.x, a.y, a.z, a.w};
            float bvv[4] = {bb.x, bb.y, bb.z, bb.w};
            #pragma unroll
            for (int i = 0; i < 4; i++)
                #pragma unroll
                for (int j = 0; j < 4; j++)
                    acc[i][j] = fmaf(av[i], bvv[j], acc[i][j]);
        }
        __syncthreads();
    }

    #pragma unroll
    for (int i = 0; i < 4; i++) {
        const int row = m0 + ty*4 + i;
        const float bv = bias[row];
        const size_t off = (size_t)b*CH*HWN + (size_t)row*HWN + n0 + tx*4;
        float4 o;
        o.x = acc[i][0] + bv; o.y = acc[i][1] + bv;
        o.z = acc[i][2] + bv; o.w = acc[i][3] + bv;
        if (res) {
            float4 r = *(const float4*)&res[off];
            o.x += r.x; o.y += r.y; o.z += r.z; o.w += r.w;
        }
        *(float4*)&Y[off] = o;
    }
}

// =====================================================================
// Flash attention, one (b,h) per blockIdx.y, 64-query tile per blockIdx.x.
// Q/K/V stored as [b][h*64+d][n] fp32 (from g_q/g_k/g_v).
// SMEM: Qs,Ks,Vs 64x64 [d][m], Ps 64x65 [n][m], alphas 64.
// Threads: 256 (16x16). S-threads own (n=ty*4.., m=tx*4..);
// O-threads own (d=ty*4.., n=tx*4..).
// =====================================================================
#define ATTN_SMEM ((3*4096 + 64*65 + 64) * sizeof(float))

__global__ void attn_kernel()
{
    extern __shared__ float sm[];
    float* Qs = sm;                 // [d*64 + n]
    float* Ks = Qs + 4096;          // [d*64 + m]
    float* Vs = Ks + 4096;          // [d*64 + m]
    float* Ps = Vs + 4096;          // [n*65 + m]
    float* alphas = Ps + 64*65;     // [n]

    const int bh = blockIdx.y;
    const int b = bh >> 2, h = bh & 3;
    const int n0 = blockIdx.x * 64;
    const size_t head_off = ((size_t)b*CH + (size_t)h*HD) * HWN;
    const float* Qg = g_q + head_off;
    const float* Kg = g_k + head_off;
    const float* Vg = g_v + head_off;

    const int t = threadIdx.x;
    const int tx = t & 15, ty = t >> 4;
    const float scale = 0.125f;     // hd^-0.5

    // load Q tile (pre-scaled)
    for (int i4 = t; i4 < 1024; i4 += 256) {
        int d = i4 >> 4, nf = (i4 & 15) * 4;
        float4 v = *(const float4*)&Qg[(size_t)d*HWN + n0 + nf];
        v.x *= scale; v.y *= scale; v.z *= scale; v.w *= scale;
        *(float4*)&Qs[d*64 + nf] = v;
    }
    __syncthreads();

    float mreg[4], lreg[4], o[4][4] = {};
    #pragma unroll
    for (int i = 0; i < 4; i++) { mreg[i] = -INFINITY; lreg[i] = 0.f; }

    for (int j0 = 0; j0 < HWN; j0 += 64) {
        // load K,V tiles
        for (int i4 = t; i4 < 1024; i4 += 256) {
            int d = i4 >> 4, mf = (i4 & 15) * 4;
            *(float4*)&Ks[d*64 + mf] = *(const float4*)&Kg[(size_t)d*HWN + j0 + mf];
            *(float4*)&Vs[d*64 + mf] = *(const float4*)&Vg[(size_t)d*HWN + j0 + mf];
        }
        __syncthreads();

        // S = Q^T K
        float s[4][4] = {};
        #pragma unroll 16
        for (int d = 0; d < 64; d++) {
            float4 a = *(const float4*)&Qs[d*64 + ty*4];
            float4 k = *(const float4*)&Ks[d*64 + tx*4];
            float av[4] = {a.x, a.y, a.z, a.w};
            float kv[4] = {k.x, k.y, k.z, k.w};
            #pragma unroll
            for (int i = 0; i < 4; i++)
                #pragma unroll
                for (int j = 0; j < 4; j++)
                    s[i][j] = fmaf(av[i], kv[j], s[i][j]);
        }

        // online softmax (per row n)
        float rowmax[4], rowsum[4], newm[4], alpha[4];
        #pragma unroll
        for (int i = 0; i < 4; i++)
            rowmax[i] = fmaxf(fmaxf(s[i][0], s[i][1]), fmaxf(s[i][2], s[i][3]));
        #pragma unroll
        for (int off = 8; off >= 1; off >>= 1)
            #pragma unroll
            for (int i = 0; i < 4; i++)
                rowmax[i] = fmaxf(rowmax[i], __shfl_xor_sync(0xffffffffu, rowmax[i], off));
        #pragma unroll
        for (int i = 0; i < 4; i++) {
            newm[i]  = fmaxf(mreg[i], rowmax[i]);
            alpha[i] = __expf(mreg[i] - newm[i]);
        }
        #pragma unroll
        for (int i = 0; i < 4; i++) {
            #pragma unroll
            for (int j = 0; j < 4; j++)
                s[i][j] = __expf(s[i][j] - newm[i]);
            rowsum[i] = s[i][0] + s[i][1] + s[i][2] + s[i][3];
        }
        #pragma unroll
        for (int off = 8; off >= 1; off >>= 1)
            #pragma unroll
            for (int i = 0; i < 4; i++)
                rowsum[i] += __shfl_xor_sync(0xffffffffu, rowsum[i], off);
        #pragma unroll
        for (int i = 0; i < 4; i++) {
            lreg[i] = lreg[i]*alpha[i] + rowsum[i];
            mreg[i] = newm[i];
        }
        if (tx == 0)
            #pragma unroll
            for (int i = 0; i < 4; i++) alphas[ty*4+i] = alpha[i];
        #pragma unroll
        for (int i = 0; i < 4; i++)
            #pragma unroll
            for (int j = 0; j < 4; j++)
                Ps[(ty*4+i)*65 + tx*4+j] = s[i][j];
        __syncthreads();

        // O = O*alpha + V P^T   (thread owns d=ty*4.., n=tx*4..)
        float av2[4];
        #pragma unroll
        for (int j = 0; j < 4; j++) av2[j] = alphas[tx*4+j];
        #pragma unroll
        for (int i = 0; i < 4; i++)
            #pragma unroll
            for (int j = 0; j < 4; j++)
                o[i][j] *= av2[j];

        for (int m4 = 0; m4 < 64; m4 += 4) {
            float4 v4[4];
            #pragma unroll
            for (int i = 0; i < 4; i++)
                v4[i] = *(const float4*)&Vs[(ty*4+i)*64 + m4];
            float vv[4][4];
            #pragma unroll
            for (int i = 0; i < 4; i++) {
                vv[i][0]=v4[i].x; vv[i][1]=v4[i].y; vv[i][2]=v4[i].z; vv[i][3]=v4[i].w;
            }
            #pragma unroll
            for (int mm = 0; mm < 4; mm++) {
                float p[4];
                #pragma unroll
                for (int j = 0; j < 4; j++)
                    p[j] = Ps[(tx*4+j)*65 + m4 + mm];
                #pragma unroll
                for (int i = 0; i < 4; i++)
                    #pragma unroll
                    for (int j = 0; j < 4; j++)
                        o[i][j] = fmaf(vv[i][mm], p[j], o[i][j]);
            }
        }
        __syncthreads();
    }

    // final normalize & store
    if (tx == 0)
        #pragma unroll
        for (int i = 0; i < 4; i++) alphas[ty*4+i] = lreg[i];
    __syncthreads();
    float linv[4];
    #pragma unroll
    for (int j = 0; j < 4; j++) linv[j] = 1.f / alphas[tx*4+j];

    float* Og = g_ao + head_off;
    #pragma unroll
    for (int i = 0; i < 4; i++) {
        float4 ov;
        ov.x = o[i][0]*linv[0]; ov.y = o[i][1]*linv[1];
        ov.z = o[i][2]*linv[2]; ov.w = o[i][3]*linv[3];
        *(float4*)&Og[(size_t)(ty*4+i)*HWN + n0 + tx*4] = ov;
    }
}

// =====================================================================
extern "C" void kernel_launch(void* const* d_in, const int* in_sizes, int n_in,
                              void* d_out, int out_size)
{
    const float* x    = (const float*)d_in[0];
    const float* cond = (const float*)d_in[1];
    const float* gqw  = (const float*)d_in[2];
    const float* gqb  = (const float*)d_in[3];
    const float* gkw  = (const float*)d_in[4];
    const float* gkb  = (const float*)d_in[5];
    const float* wq   = (const float*)d_in[6];
    const float* bq   = (const float*)d_in[7];
    const float* wk   = (const float*)d_in[8];
    const float* bk   = (const float*)d_in[9];
    const float* wv   = (const float*)d_in[10];
    const float* bv   = (const float*)d_in[11];
    const float* wo   = (const float*)d_in[12];
    const float* bo   = (const float*)d_in[13];
    float* out = (float*)d_out;

    float *p_xn, *p_kvn, *p_q, *p_k, *p_v, *p_ao;
    cudaGetSymbolAddress((void**)&p_xn,  g_xn);
    cudaGetSymbolAddress((void**)&p_kvn, g_kvn);
    cudaGetSymbolAddress((void**)&p_q,   g_q);
    cudaGetSymbolAddress((void**)&p_k,   g_k);
    cudaGetSymbolAddress((void**)&p_v,   g_v);
    cudaGetSymbolAddress((void**)&p_ao,  g_ao);

    cudaFuncSetAttribute(attn_kernel,
                         cudaFuncAttributeMaxDynamicSharedMemorySize,
                         (int)ATTN_SMEM);

    // 1) GroupNorms
    gn_kernel<<<dim3(BATCH*GROUPS, 2), 256>>>(x, cond, gqw, gqb, gkw, gkb);

    // 2) q / k / v projections
    dim3 ggrid(HWN/64, CH/64, BATCH);
    gemm_kernel<<<ggrid, 256>>>(wq, p_xn,  bq, nullptr, p_q);
    gemm_kernel<<<ggrid, 256>>>(wk, p_kvn, bk, nullptr, p_k);
    gemm_kernel<<<ggrid, 256>>>(wv, p_kvn, bv, nullptr, p_v);

    // 3) attention
    attn_kernel<<<dim3(HWN/64, BATCH*NHEADS), 256, ATTN_SMEM>>>();

    // 4) output projection + residual
    gemm_kernel<<<ggrid, 256>>>(wo, p_ao, bo, x, out);
}

// round 2
// speedup vs baseline: 1.9870x; 1.9870x over previous
#include <cuda_runtime.h>
#include <math.h>

#define BATCH 4
#define CH    256
#define HWN   4096      // H*W
#define GROUPS 32
#define CPG    8        // CH/GROUPS
#define NHEADS 4
#define HD     64
#define EPSV   1e-5f

// ---- scratch (allocation-free: __device__ globals) ----
__device__ float g_xn [BATCH*CH*HWN];
__device__ float g_kvn[BATCH*CH*HWN];
__device__ float g_q  [BATCH*CH*HWN];
__device__ float g_k  [BATCH*CH*HWN];
__device__ float g_v  [BATCH*CH*HWN];
__device__ float g_ao [BATCH*CH*HWN];

// =====================================================================
// GroupNorm
// =====================================================================
__global__ void gn_kernel(const float* __restrict__ x,
                          const float* __restrict__ cond,
                          const float* __restrict__ gqw, const float* __restrict__ gqb,
                          const float* __restrict__ gkw, const float* __restrict__ gkb)
{
    const int kv = blockIdx.y;
    const float* in  = kv ? cond : x;
    float*       out = kv ? g_kvn : g_xn;
    const float* gw  = kv ? gkw : gqw;
    const float* gb  = kv ? gkb : gqb;

    const int b = blockIdx.x / GROUPS;
    const int g = blockIdx.x % GROUPS;
    const size_t base_off = ((size_t)b*CH + (size_t)g*CPG) * HWN;
    const float4* in4  = (const float4*)(in  + base_off);
    float4*       out4 = (float4*)(out + base_off);

    float s = 0.f, ss = 0.f;
    for (int i = threadIdx.x; i < (CPG*HWN)/4; i += 256) {
        float4 v = in4[i];
        s  += v.x + v.y + v.z + v.w;
        ss += v.x*v.x + v.y*v.y + v.z*v.z + v.w*v.w;
    }
    #pragma unroll
    for (int off = 16; off; off >>= 1) {
        s  += __shfl_xor_sync(0xffffffffu, s,  off);
        ss += __shfl_xor_sync(0xffffffffu, ss, off);
    }
    __shared__ float sm_s[8], sm_ss[8];
    if ((threadIdx.x & 31) == 0) { sm_s[threadIdx.x>>5] = s; sm_ss[threadIdx.x>>5] = ss; }
    __syncthreads();
    s = 0.f; ss = 0.f;
    #pragma unroll
    for (int w = 0; w < 8; w++) { s += sm_s[w]; ss += sm_ss[w]; }

    const float inv_n = 1.f / (float)(CPG*HWN);
    const float mean  = s * inv_n;
    const float var   = ss * inv_n - mean*mean;
    const float rstd  = rsqrtf(var + EPSV);

    for (int i = threadIdx.x; i < (CPG*HWN)/4; i += 256) {
        int ch = i >> 10;
        float gwv = gw[g*CPG + ch];
        float gbv = gb[g*CPG + ch];
        float4 v = in4[i];
        float4 o;
        o.x = (v.x - mean)*rstd*gwv + gbv;
        o.y = (v.y - mean)*rstd*gwv + gbv;
        o.z = (v.z - mean)*rstd*gwv + gbv;
        o.w = (v.w - mean)*rstd*gwv + gbv;
        out4[i] = o;
    }
}

// =====================================================================
// 1x1-conv GEMM (fp32 SIMT, unchanged this round)
// =====================================================================
__global__ void gemm_kernel(const float* __restrict__ W,
                            const float* __restrict__ X,
                            const float* __restrict__ bias,
                            const float* __restrict__ res,
                            float* __restrict__ Y)
{
    const int b  = blockIdx.z;
    const int m0 = blockIdx.y * 64;
    const int n0 = blockIdx.x * 64;
    const float* Xb = X + (size_t)b*CH*HWN;

    __shared__ float Wts[16][68];
    __shared__ float Xs [16][64];

    const int t  = threadIdx.x;
    const int tx = t & 15, ty = t >> 4;
    const int wr = t >> 2, wc4 = (t & 3) * 4;
    const int xr = t >> 4, xc4 = (t & 15) * 4;

    float acc[4][4] = {};

    for (int k0 = 0; k0 < CH; k0 += 16) {
        float4 wv = *(const float4*)&W[(size_t)(m0+wr)*CH + k0 + wc4];
        Wts[wc4+0][wr] = wv.x;
        Wts[wc4+1][wr] = wv.y;
        Wts[wc4+2][wr] = wv.z;
        Wts[wc4+3][wr] = wv.w;
        *(float4*)&Xs[xr][xc4] =
            *(const float4*)&Xb[(size_t)(k0+xr)*HWN + n0 + xc4];
        __syncthreads();
        #pragma unroll
        for (int kk = 0; kk < 16; kk++) {
            float4 a  = *(const float4*)&Wts[kk][ty*4];
            float4 bb = *(const float4*)&Xs[kk][tx*4];
            float av[4] = {a.x, a.y, a.z, a.w};
            float bvv[4] = {bb.x, bb.y, bb.z, bb.w};
            #pragma unroll
            for (int i = 0; i < 4; i++)
                #pragma unroll
                for (int j = 0; j < 4; j++)
                    acc[i][j] = fmaf(av[i], bvv[j], acc[i][j]);
        }
        __syncthreads();
    }

    #pragma unroll
    for (int i = 0; i < 4; i++) {
        const int row = m0 + ty*4 + i;
        const float bv = bias[row];
        const size_t off = (size_t)b*CH*HWN + (size_t)row*HWN + n0 + tx*4;
        float4 o;
        o.x = acc[i][0] + bv; o.y = acc[i][1] + bv;
        o.z = acc[i][2] + bv; o.w = acc[i][3] + bv;
        if (res) {
            float4 r = *(const float4*)&res[off];
            o.x += r.x; o.y += r.y; o.z += r.z; o.w += r.w;
        }
        *(float4*)&Y[off] = o;
    }
}

// =====================================================================
// TF32 tensor-core flash attention.
// Block: 128 queries of one (b,h); 8 warps; warp = 16-query stripe.
// m16n8k8 tf32 mma: groupID = lane>>2 (rows), tid = lane&3 (cols).
// =====================================================================
__device__ __forceinline__ float fast_exp2(float x) {
    float y;
    asm("ex2.approx.f32 %0, %1;" : "=f"(y) : "f"(x));
    return y;
}

__device__ __forceinline__ void mma_tf32(float* d, const float* a, float b0, float b1) {
    asm volatile(
        "mma.sync.aligned.m16n8k8.row.col.f32.tf32.tf32.f32 "
        "{%0,%1,%2,%3}, {%4,%5,%6,%7}, {%8,%9}, {%0,%1,%2,%3};\n"
        : "+f"(d[0]), "+f"(d[1]), "+f"(d[2]), "+f"(d[3])
        : "r"(__float_as_uint(a[0])), "r"(__float_as_uint(a[1])),
          "r"(__float_as_uint(a[2])), "r"(__float_as_uint(a[3])),
          "r"(__float_as_uint(b0)),   "r"(__float_as_uint(b1)));
}

#define KS_STR 72
#define VS_STR 68
#define PS_STR 72
#define QS_STR 132
#define ATTN_SMEM ((64*KS_STR + 64*VS_STR + 128*PS_STR) * sizeof(float))

__global__ void __launch_bounds__(256, 1) attn_mma_kernel()
{
    extern __shared__ float sm[];
    float* Ks = sm;                    // [64 d][KS_STR]  (m along row)
    float* Vs = Ks + 64*KS_STR;        // [64 d][VS_STR]
    float* Ps = Vs + 64*VS_STR;        // [128 n][PS_STR]; also Q stage [64][QS_STR]

    const int bh = blockIdx.y;
    const int b  = bh >> 2, h = bh & 3;
    const int n0 = blockIdx.x * 128;
    const size_t head_off = ((size_t)b*CH + (size_t)h*HD) * HWN;
    const float* Qg = g_q + head_off;
    const float* Kg = g_k + head_off;
    const float* Vg = g_v + head_off;

    const int t    = threadIdx.x;
    const int lane = t & 31, warp = t >> 5;
    const int g    = lane >> 2, tid = lane & 3;

    const float qscale = 0.125f * 1.4426950408889634f;  // hd^-0.5 * log2(e)

    // ---- stage Q tile (64 d x 128 n), pre-scaled ----
    for (int i = t; i < 64*32; i += 256) {
        int d = i >> 5, nf = (i & 31) * 4;
        float4 v = *(const float4*)&Qg[(size_t)d*HWN + n0 + nf];
        v.x *= qscale; v.y *= qscale; v.z *= qscale; v.w *= qscale;
        *(float4*)&Ps[d*QS_STR + nf] = v;
    }
    __syncthreads();

    // ---- Q A-fragments: persistent in registers (row = n, col = d) ----
    float qa[8][4];
    {
        const int nb = warp*16 + g;
        #pragma unroll
        for (int kc = 0; kc < 8; kc++) {
            const int d0 = kc*8 + tid;
            qa[kc][0] = Ps[d0*QS_STR + nb];
            qa[kc][1] = Ps[d0*QS_STR + nb + 8];
            qa[kc][2] = Ps[(d0+4)*QS_STR + nb];
            qa[kc][3] = Ps[(d0+4)*QS_STR + nb + 8];
        }
    }
    __syncthreads();   // done with Q stage; Ps region may be reused

    float mr0 = -INFINITY, mr1 = -INFINITY, lr0 = 0.f, lr1 = 0.f;
    float oa[8][4];
    #pragma unroll
    for (int i = 0; i < 8; i++)
        #pragma unroll
        for (int j = 0; j < 4; j++) oa[i][j] = 0.f;

    float* Pw = Ps + warp*16*PS_STR;   // warp-private P slice

    for (int j0 = 0; j0 < HWN; j0 += 64) {
        // ---- load K,V tiles (64 d x 64 m) ----
        for (int i = t; i < 64*16; i += 256) {
            int d = i >> 4, mf = (i & 15) * 4;
            *(float4*)&Ks[d*KS_STR + mf] = *(const float4*)&Kg[(size_t)d*HWN + j0 + mf];
            *(float4*)&Vs[d*VS_STR + mf] = *(const float4*)&Vg[(size_t)d*HWN + j0 + mf];
        }
        __syncthreads();

        // ---- S = Q^T K  (16 n x 64 m per warp) ----
        float sa[8][4];
        #pragma unroll
        for (int mt = 0; mt < 8; mt++)
            #pragma unroll
            for (int j = 0; j < 4; j++) sa[mt][j] = 0.f;

        #pragma unroll
        for (int kc = 0; kc < 8; kc++) {
            const int r0 = (kc*8 + tid)*KS_STR;
            const int r1 = (kc*8 + tid + 4)*KS_STR;
            #pragma unroll
            for (int mt = 0; mt < 8; mt++) {
                float b0 = Ks[r0 + mt*8 + g];
                float b1 = Ks[r1 + mt*8 + g];
                mma_tf32(sa[mt], qa[kc], b0, b1);
            }
        }

        // ---- online softmax (rows g, g+8; base-2 domain) ----
        float mx0 = -INFINITY, mx1 = -INFINITY;
        #pragma unroll
        for (int mt = 0; mt < 8; mt++) {
            mx0 = fmaxf(mx0, fmaxf(sa[mt][0], sa[mt][1]));
            mx1 = fmaxf(mx1, fmaxf(sa[mt][2], sa[mt][3]));
        }
        mx0 = fmaxf(mx0, __shfl_xor_sync(0xffffffffu, mx0, 1));
        mx0 = fmaxf(mx0, __shfl_xor_sync(0xffffffffu, mx0, 2));
        mx1 = fmaxf(mx1, __shfl_xor_sync(0xffffffffu, mx1, 1));
        mx1 = fmaxf(mx1, __shfl_xor_sync(0xffffffffu, mx1, 2));

        const float nm0 = fmaxf(mr0, mx0);
        const float nm1 = fmaxf(mr1, mx1);
        const float al0 = fast_exp2(mr0 - nm0);
        const float al1 = fast_exp2(mr1 - nm1);

        float rs0 = 0.f, rs1 = 0.f;
        #pragma unroll
        for (int mt = 0; mt < 8; mt++) {
            sa[mt][0] = fast_exp2(sa[mt][0] - nm0);
            sa[mt][1] = fast_exp2(sa[mt][1] - nm0);
            sa[mt][2] = fast_exp2(sa[mt][2] - nm1);
            sa[mt][3] = fast_exp2(sa[mt][3] - nm1);
            rs0 += sa[mt][0] + sa[mt][1];
            rs1 += sa[mt][2] + sa[mt][3];
        }
        rs0 += __shfl_xor_sync(0xffffffffu, rs0, 1);
        rs0 += __shfl_xor_sync(0xffffffffu, rs0, 2);
        rs1 += __shfl_xor_sync(0xffffffffu, rs1, 1);
        rs1 += __shfl_xor_sync(0xffffffffu, rs1, 2);

        lr0 = lr0*al0 + rs0;  lr1 = lr1*al1 + rs1;
        mr0 = nm0;            mr1 = nm1;

        #pragma unroll
        for (int dt = 0; dt < 8; dt++) {
            oa[dt][0] *= al0; oa[dt][1] *= al0;
            oa[dt][2] *= al1; oa[dt][3] *= al1;
        }

        // ---- stage P (C-frag -> A-frag reshape through warp-private SMEM) ----
        #pragma unroll
        for (int mt = 0; mt < 8; mt++) {
            *(float2*)&Pw[g*PS_STR + mt*8 + tid*2]     = make_float2(sa[mt][0], sa[mt][1]);
            *(float2*)&Pw[(g+8)*PS_STR + mt*8 + tid*2] = make_float2(sa[mt][2], sa[mt][3]);
        }
        __syncwarp();

        // ---- O' += P V^T  (16 n x 64 d per warp) ----
        #pragma unroll
        for (int kc = 0; kc < 8; kc++) {
            float pa[4];
            pa[0] = Pw[g*PS_STR + kc*8 + tid];
            pa[1] = Pw[(g+8)*PS_STR + kc*8 + tid];
            pa[2] = Pw[g*PS_STR + kc*8 + tid + 4];
            pa[3] = Pw[(g+8)*PS_STR + kc*8 + tid + 4];
            #pragma unroll
            for (int dt = 0; dt < 8; dt++) {
                float b0 = Vs[(dt*8+g)*VS_STR + kc*8 + tid];
                float b1 = Vs[(dt*8+g)*VS_STR + kc*8 + tid + 4];
                mma_tf32(oa[dt], pa, b0, b1);
            }
        }
        __syncthreads();
    }

    // ---- normalize, transpose through SMEM, store [d][n] ----
    const float il0 = 1.f / lr0;
    const float il1 = 1.f / lr1;
    #pragma unroll
    for (int dt = 0; dt < 8; dt++) {
        *(float2*)&Pw[g*PS_STR + dt*8 + tid*2]     = make_float2(oa[dt][0]*il0, oa[dt][1]*il0);
        *(float2*)&Pw[(g+8)*PS_STR + dt*8 + tid*2] = make_float2(oa[dt][2]*il1, oa[dt][3]*il1);
    }
    __syncthreads();

    float* Og = g_ao + head_off;
    for (int i = t; i < 64*128; i += 256) {
        int d = i >> 7, n = i & 127;
        Og[(size_t)d*HWN + n0 + n] = Ps[n*PS_STR + d];
    }
    // remaining rows handled by loop (64 d * 128 n / 256 = 32 iters/thread)
}

// =====================================================================
extern "C" void kernel_launch(void* const* d_in, const int* in_sizes, int n_in,
                              void* d_out, int out_size)
{
    const float* x    = (const float*)d_in[0];
    const float* cond = (const float*)d_in[1];
    const float* gqw  = (const float*)d_in[2];
    const float* gqb  = (const float*)d_in[3];
    const float* gkw  = (const float*)d_in[4];
    const float* gkb  = (const float*)d_in[5];
    const float* wq   = (const float*)d_in[6];
    const float* bq   = (const float*)d_in[7];
    const float* wk   = (const float*)d_in[8];
    const float* bk   = (const float*)d_in[9];
    const float* wv   = (const float*)d_in[10];
    const float* bv   = (const float*)d_in[11];
    const float* wo   = (const float*)d_in[12];
    const float* bo   = (const float*)d_in[13];
    float* out = (float*)d_out;

    float *p_xn, *p_kvn, *p_q, *p_k, *p_v, *p_ao;
    cudaGetSymbolAddress((void**)&p_xn,  g_xn);
    cudaGetSymbolAddress((void**)&p_kvn, g_kvn);
    cudaGetSymbolAddress((void**)&p_q,   g_q);
    cudaGetSymbolAddress((void**)&p_k,   g_k);
    cudaGetSymbolAddress((void**)&p_v,   g_v);
    cudaGetSymbolAddress((void**)&p_ao,  g_ao);

    cudaFuncSetAttribute(attn_mma_kernel,
                         cudaFuncAttributeMaxDynamicSharedMemorySize,
                         (int)ATTN_SMEM);

    gn_kernel<<<dim3(BATCH*GROUPS, 2), 256>>>(x, cond, gqw, gqb, gkw, gkb);

    dim3 ggrid(HWN/64, CH/64, BATCH);
    gemm_kernel<<<ggrid, 256>>>(wq, p_xn,  bq, nullptr, p_q);
    gemm_kernel<<<ggrid, 256>>>(wk, p_kvn, bk, nullptr, p_k);
    gemm_kernel<<<ggrid, 256>>>(wv, p_kvn, bv, nullptr, p_v);

    attn_mma_kernel<<<dim3(HWN/128, BATCH*NHEADS), 256, ATTN_SMEM>>>();

    gemm_kernel<<<ggrid, 256>>>(wo, p_ao, bo, x, out);
}

// round 5
// speedup vs baseline: 3.8228x; 1.9239x over previous
#include <cuda_runtime.h>
#include <cuda_bf16.h>
#include <math.h>
#include <stdint.h>

#define BATCH 4
#define CH    256
#define HWN   4096
#define GROUPS 32
#define CPG   8
#define NHEADS 4
#define HD    64
#define EPSV  1e-5f
#define QSCALE 0.18033688011112042f   // 0.125 * log2(e)

// ---- scratch (__device__ globals; allocation-free) ----
__device__ float g_xn [BATCH*CH*HWN];
__device__ float g_kvn[BATCH*CH*HWN];
__device__ float g_ao [BATCH*CH*HWN];
__device__ __nv_bfloat16 g_qb[BATCH*CH*HWN];   // [b][h][n][d], pre-scaled by QSCALE
__device__ __nv_bfloat16 g_kb[BATCH*CH*HWN];   // [b][h][n][d]
__device__ __nv_bfloat16 g_vb[BATCH*CH*HWN];   // [b][c=h*64+d][n]

__device__ __forceinline__ float fast_exp2(float x) {
    float y; asm("ex2.approx.f32 %0, %1;" : "=f"(y) : "f"(x)); return y;
}
__device__ __forceinline__ uint32_t pack_bf16x2(float lo, float hi) {
    uint32_t r;
    asm("cvt.rn.satfinite.bf16x2.f32 %0, %1, %2;" : "=r"(r) : "f"(hi), "f"(lo));
    return r;
}
__device__ __forceinline__ void mma_bf16(float* d, const uint32_t* a,
                                         uint32_t b0, uint32_t b1) {
    asm volatile(
        "mma.sync.aligned.m16n8k16.row.col.f32.bf16.bf16.f32 "
        "{%0,%1,%2,%3}, {%4,%5,%6,%7}, {%8,%9}, {%0,%1,%2,%3};\n"
        : "+f"(d[0]), "+f"(d[1]), "+f"(d[2]), "+f"(d[3])
        : "r"(a[0]), "r"(a[1]), "r"(a[2]), "r"(a[3]), "r"(b0), "r"(b1));
}

// =====================================================================
// GroupNorm
// =====================================================================
__global__ void gn_kernel(const float* __restrict__ x,
                          const float* __restrict__ cond,
                          const float* __restrict__ gqw, const float* __restrict__ gqb,
                          const float* __restrict__ gkw, const float* __restrict__ gkb)
{
    const int kv = blockIdx.y;
    const float* in  = kv ? cond : x;
    float*       out = kv ? g_kvn : g_xn;
    const float* gw  = kv ? gkw : gqw;
    const float* gb  = kv ? gkb : gqb;

    const int b = blockIdx.x / GROUPS;
    const int g = blockIdx.x % GROUPS;
    const size_t base_off = ((size_t)b*CH + (size_t)g*CPG) * HWN;
    const float4* in4  = (const float4*)(in  + base_off);
    float4*       out4 = (float4*)(out + base_off);

    float s = 0.f, ss = 0.f;
    for (int i = threadIdx.x; i < (CPG*HWN)/4; i += 256) {
        float4 v = in4[i];
        s  += v.x + v.y + v.z + v.w;
        ss += v.x*v.x + v.y*v.y + v.z*v.z + v.w*v.w;
    }
    #pragma unroll
    for (int off = 16; off; off >>= 1) {
        s  += __shfl_xor_sync(0xffffffffu, s,  off);
        ss += __shfl_xor_sync(0xffffffffu, ss, off);
    }
    __shared__ float sm_s[8], sm_ss[8];
    if ((threadIdx.x & 31) == 0) { sm_s[threadIdx.x>>5] = s; sm_ss[threadIdx.x>>5] = ss; }
    __syncthreads();
    s = 0.f; ss = 0.f;
    #pragma unroll
    for (int w = 0; w < 8; w++) { s += sm_s[w]; ss += sm_ss[w]; }

    const float inv_n = 1.f / (float)(CPG*HWN);
    const float mean  = s * inv_n;
    const float var   = ss * inv_n - mean*mean;
    const float rstd  = rsqrtf(var + EPSV);

    for (int i = threadIdx.x; i < (CPG*HWN)/4; i += 256) {
        int ch = i >> 10;
        float gwv = gw[g*CPG + ch];
        float gbv = gb[g*CPG + ch];
        float4 v = in4[i];
        float4 o;
        o.x = (v.x - mean)*rstd*gwv + gbv;
        o.y = (v.y - mean)*rstd*gwv + gbv;
        o.z = (v.z - mean)*rstd*gwv + gbv;
        o.w = (v.w - mean)*rstd*gwv + gbv;
        out4[i] = o;
    }
}

// =====================================================================
// 1x1 GEMM (fp32 SIMT). mode epilogue:
//  0: fp32 [c][n] + residual   1: bf16 q [b][h][n][d]*QSCALE
//  2: bf16 k [b][h][n][d]      3: bf16 v [b][c][n]
// =====================================================================
__global__ void gemm_kernel(const float* __restrict__ W,
                            const float* __restrict__ X,
                            const float* __restrict__ bias,
                            const float* __restrict__ res,
                            float* __restrict__ outf,
                            __nv_bfloat16* __restrict__ outb,
                            int mode)
{
    const int b  = blockIdx.z;
    const int m0 = blockIdx.y * 64;
    const int n0 = blockIdx.x * 64;
    const float* Xb = X + (size_t)b*CH*HWN;

    __shared__ float Wts[16][68];
    __shared__ float Xs [16][64];

    const int t  = threadIdx.x;
    const int tx = t & 15, ty = t >> 4;
    const int wr = t >> 2, wc4 = (t & 3) * 4;
    const int xr = t >> 4, xc4 = (t & 15) * 4;

    float acc[4][4] = {};

    for (int k0 = 0; k0 < CH; k0 += 16) {
        float4 wv = *(const float4*)&W[(size_t)(m0+wr)*CH + k0 + wc4];
        Wts[wc4+0][wr] = wv.x;
        Wts[wc4+1][wr] = wv.y;
        Wts[wc4+2][wr] = wv.z;
        Wts[wc4+3][wr] = wv.w;
        *(float4*)&Xs[xr][xc4] =
            *(const float4*)&Xb[(size_t)(k0+xr)*HWN + n0 + xc4];
        __syncthreads();
        #pragma unroll
        for (int kk = 0; kk < 16; kk++) {
            float4 a  = *(const float4*)&Wts[kk][ty*4];
            float4 bb = *(const float4*)&Xs[kk][tx*4];
            float av[4] = {a.x, a.y, a.z, a.w};
            float bv2[4] = {bb.x, bb.y, bb.z, bb.w};
            #pragma unroll
            for (int i = 0; i < 4; i++)
                #pragma unroll
                for (int j = 0; j < 4; j++)
                    acc[i][j] = fmaf(av[i], bv2[j], acc[i][j]);
        }
        __syncthreads();
    }

    #pragma unroll
    for (int i = 0; i < 4; i++) {
        const int row = m0 + ty*4 + i;
        const float bv = bias[row];
        if (mode == 0) {
            const size_t off = (size_t)b*CH*HWN + (size_t)row*HWN + n0 + tx*4;
            float4 o;
            o.x = acc[i][0] + bv; o.y = acc[i][1] + bv;
            o.z = acc[i][2] + bv; o.w = acc[i][3] + bv;
            float4 r = *(const float4*)&res[off];
            o.x += r.x; o.y += r.y; o.z += r.z; o.w += r.w;
            *(float4*)&outf[off] = o;
        } else if (mode == 3) {
            const size_t off = (size_t)b*CH*HWN + (size_t)row*HWN + n0 + tx*4;
            #pragma unroll
            for (int j = 0; j < 4; j++)
                outb[off + j] = __float2bfloat16_rn(acc[i][j] + bv);
        } else {
            const float sc = (mode == 1) ? QSCALE : 1.0f;
            const int hh = row >> 6, dd = row & 63;
            const size_t base = ((size_t)(b*NHEADS + hh)*HWN + n0 + tx*4) * HD + dd;
            #pragma unroll
            for (int j = 0; j < 4; j++)
                outb[base + (size_t)j*HD] = __float2bfloat16_rn((acc[i][j] + bv) * sc);
        }
    }
}

// =====================================================================
// bf16 mma.sync flash attention (no online max: logits bounded).
// Block = 128 queries of one (b,h); 8 warps x 16 queries.
// m16n8k16: g=lane>>2 (rows), tid=lane&3.
//  A-frag: a0=(g,2t..2t+1) a1=(g+8,..) a2=(g,2t+8..) a3=(g+8,2t+8..)
//  B-frag: b0=(k=2t..2t+1, n=g) b1=(k=2t+8.., n=g)
//  C-frag: c0=(g,2t) c1=(g,2t+1) c2=(g+8,2t) c3=(g+8,2t+1)
// =====================================================================
#define KS_STR 72   // bf16 units
#define PS_STR 72
#define OW_STR 65   // f32 units

__global__ void __launch_bounds__(256, 2) attn_mma_bf16()
{
    __shared__ char smbuf[36864];
    __nv_bfloat16* Ks = (__nv_bfloat16*)smbuf;   // [64 key][KS_STR d]
    __nv_bfloat16* Vs = Ks + 64*KS_STR;          // [64 d][KS_STR key]
    __nv_bfloat16* Ps = Vs + 64*KS_STR;          // 8 warps x [16 n][PS_STR m]
    float*         Ow = (float*)smbuf;           // [128 n][OW_STR d] (reused)

    const int bh = blockIdx.y;
    const int b = bh >> 2, h = bh & 3;
    const int n0 = blockIdx.x * 128;
    const __nv_bfloat16* Qg = g_qb + (size_t)(b*NHEADS + h) * HWN * HD;
    const __nv_bfloat16* Kg = g_kb + (size_t)(b*NHEADS + h) * HWN * HD;
    const __nv_bfloat16* Vg = g_vb + ((size_t)b*CH + (size_t)h*HD) * HWN;

    const int t = threadIdx.x;
    const int lane = t & 31, warp = t >> 5;
    const int g = lane >> 2, tid = lane & 3;
    const int nb = warp * 16;

    // ---- Q A-fragments straight from gmem (persist whole block) ----
    uint32_t qa[4][4];
    {
        const __nv_bfloat16* q0 = Qg + (size_t)(n0 + nb + g) * HD;
        const __nv_bfloat16* q1 = Qg + (size_t)(n0 + nb + g + 8) * HD;
        #pragma unroll
        for (int kc = 0; kc < 4; kc++) {
            qa[kc][0] = *(const uint32_t*)(q0 + kc*16 + 2*tid);
            qa[kc][1] = *(const uint32_t*)(q1 + kc*16 + 2*tid);
            qa[kc][2] = *(const uint32_t*)(q0 + kc*16 + 2*tid + 8);
            qa[kc][3] = *(const uint32_t*)(q1 + kc*16 + 2*tid + 8);
        }
    }

    float oa[8][4];
    #pragma unroll
    for (int i = 0; i < 8; i++)
        #pragma unroll
        for (int j = 0; j < 4; j++) oa[i][j] = 0.f;
    float ls0 = 0.f, ls1 = 0.f;

    __nv_bfloat16* Pw = Ps + warp*16*PS_STR;

    for (int j0 = 0; j0 < HWN; j0 += 64) {
        __syncthreads();
        // load K tile [64 key][64 d], V tile [64 d][64 key]
        #pragma unroll
        for (int it = 0; it < 2; it++) {
            int i = t + it*256;
            int row = i >> 3, seg = (i & 7) * 8;
            *(uint4*)(Ks + row*KS_STR + seg) =
                *(const uint4*)(Kg + (size_t)(j0 + row)*HD + seg);
            *(uint4*)(Vs + row*KS_STR + seg) =
                *(const uint4*)(Vg + (size_t)row*HWN + j0 + seg);
        }
        __syncthreads();

        // ---- S = Q K^T (16n x 64m per warp) ----
        float sa[8][4];
        #pragma unroll
        for (int mt = 0; mt < 8; mt++)
            #pragma unroll
            for (int j = 0; j < 4; j++) sa[mt][j] = 0.f;

        #pragma unroll
        for (int kc = 0; kc < 4; kc++) {
            #pragma unroll
            for (int mt = 0; mt < 8; mt++) {
                const __nv_bfloat16* kr = Ks + (mt*8 + g)*KS_STR + kc*16 + 2*tid;
                uint32_t b0 = *(const uint32_t*)kr;
                uint32_t b1 = *(const uint32_t*)(kr + 8);
                mma_bf16(sa[mt], qa[kc], b0, b1);
            }
        }

        // ---- exp2, row-sum accum, stage P (bf16) ----
        #pragma unroll
        for (int mt = 0; mt < 8; mt++) {
            float e0 = fast_exp2(sa[mt][0]);
            float e1 = fast_exp2(sa[mt][1]);
            float e2 = fast_exp2(sa[mt][2]);
            float e3 = fast_exp2(sa[mt][3]);
            ls0 += e0 + e1;
            ls1 += e2 + e3;
            *(uint32_t*)(Pw + g*PS_STR + mt*8 + 2*tid)     = pack_bf16x2(e0, e1);
            *(uint32_t*)(Pw + (g+8)*PS_STR + mt*8 + 2*tid) = pack_bf16x2(e2, e3);
        }
        __syncwarp();

        // ---- O += P V^T (16n x 64d per warp) ----
        #pragma unroll
        for (int kc = 0; kc < 4; kc++) {
            uint32_t pa[4];
            pa[0] = *(const uint32_t*)(Pw + g*PS_STR + kc*16 + 2*tid);
            pa[1] = *(const uint32_t*)(Pw + (g+8)*PS_STR + kc*16 + 2*tid);
            pa[2] = *(const uint32_t*)(Pw + g*PS_STR + kc*16 + 2*tid + 8);
            pa[3] = *(const uint32_t*)(Pw + (g+8)*PS_STR + kc*16 + 2*tid + 8);
            #pragma unroll
            for (int dt = 0; dt < 8; dt++) {
                const __nv_bfloat16* vr = Vs + (dt*8 + g)*KS_STR + kc*16 + 2*tid;
                uint32_t b0 = *(const uint32_t*)vr;
                uint32_t b1 = *(const uint32_t*)(vr + 8);
                mma_bf16(oa[dt], pa, b0, b1);
            }
        }
    }

    // ---- final row sums (reduce over tid quad) ----
    ls0 += __shfl_xor_sync(0xffffffffu, ls0, 1);
    ls0 += __shfl_xor_sync(0xffffffffu, ls0, 2);
    ls1 += __shfl_xor_sync(0xffffffffu, ls1, 1);
    ls1 += __shfl_xor_sync(0xffffffffu, ls1, 2);
    const float li0 = 1.f / ls0;
    const float li1 = 1.f / ls1;

    __syncthreads();   // before reusing smem as Ow
    #pragma unroll
    for (int dt = 0; dt < 8; dt++) {
        Ow[(nb+g)*OW_STR + dt*8 + 2*tid]     = oa[dt][0]*li0;
        Ow[(nb+g)*OW_STR + dt*8 + 2*tid + 1] = oa[dt][1]*li0;
        Ow[(nb+g+8)*OW_STR + dt*8 + 2*tid]     = oa[dt][2]*li1;
        Ow[(nb+g+8)*OW_STR + dt*8 + 2*tid + 1] = oa[dt][3]*li1;
    }
    __syncthreads();

    float* Og = g_ao + ((size_t)b*CH + (size_t)h*HD) * HWN;
    for (int i = t; i < 64*128; i += 256) {
        int d = i >> 7, n = i & 127;
        Og[(size_t)d*HWN + n0 + n] = Ow[n*OW_STR + d];
    }
}

// =====================================================================
extern "C" void kernel_launch(void* const* d_in, const int* in_sizes, int n_in,
                              void* d_out, int out_size)
{
    const float* x    = (const float*)d_in[0];
    const float* cond = (const float*)d_in[1];
    const float* gqw  = (const float*)d_in[2];
    const float* gqb  = (const float*)d_in[3];
    const float* gkw  = (const float*)d_in[4];
    const float* gkb  = (const float*)d_in[5];
    const float* wq   = (const float*)d_in[6];
    const float* bq   = (const float*)d_in[7];
    const float* wk   = (const float*)d_in[8];
    const float* bk   = (const float*)d_in[9];
    const float* wv   = (const float*)d_in[10];
    const float* bv   = (const float*)d_in[11];
    const float* wo   = (const float*)d_in[12];
    const float* bo   = (const float*)d_in[13];
    float* out = (float*)d_out;

    float *p_xn, *p_kvn, *p_ao;
    __nv_bfloat16 *p_qb, *p_kb, *p_vb;
    cudaGetSymbolAddress((void**)&p_xn,  g_xn);
    cudaGetSymbolAddress((void**)&p_kvn, g_kvn);
    cudaGetSymbolAddress((void**)&p_ao,  g_ao);
    cudaGetSymbolAddress((void**)&p_qb,  g_qb);
    cudaGetSymbolAddress((void**)&p_kb,  g_kb);
    cudaGetSymbolAddress((void**)&p_vb,  g_vb);

    gn_kernel<<<dim3(BATCH*GROUPS, 2), 256>>>(x, cond, gqw, gqb, gkw, gkb);

    dim3 ggrid(HWN/64, CH/64, BATCH);
    gemm_kernel<<<ggrid, 256>>>(wq, p_xn,  bq, nullptr, nullptr, p_qb, 1);
    gemm_kernel<<<ggrid, 256>>>(wk, p_kvn, bk, nullptr, nullptr, p_kb, 2);
    gemm_kernel<<<ggrid, 256>>>(wv, p_kvn, bv, nullptr, nullptr, p_vb, 3);

    attn_mma_bf16<<<dim3(HWN/128, BATCH*NHEADS), 256>>>();

    gemm_kernel<<<ggrid, 256>>>(wo, p_ao, bo, x, out, nullptr, 0);
}

// round 6
// speedup vs baseline: 5.4711x; 1.4312x over previous
#include <cuda_runtime.h>
#include <cuda_bf16.h>
#include <math.h>
#include <stdint.h>

#define BATCH 4
#define CH    256
#define HWN   4096
#define GROUPS 32
#define CPG   8
#define NHEADS 4
#define HD    64
#define EPSV  1e-5f
#define QSCALE 0.18033688011112042f   // 0.125 * log2(e)

// ---- scratch (__device__ globals; allocation-free) ----
__device__ float g_ao [BATCH*CH*HWN];
__device__ __nv_bfloat16 g_xnb [BATCH*HWN*CH];  // GN(x), [b][n][c]
__device__ __nv_bfloat16 g_kvnb[BATCH*HWN*CH];  // GN(cond), [b][n][c]
__device__ __nv_bfloat16 g_qb[BATCH*CH*HWN];    // [b][h][n][d], pre-scaled
__device__ __nv_bfloat16 g_kb[BATCH*CH*HWN];    // [b][h][n][d]
__device__ __nv_bfloat16 g_vb[BATCH*CH*HWN];    // [b][c][n]
__device__ __nv_bfloat16 g_wqb[CH*CH], g_wkb[CH*CH], g_wvb[CH*CH];

__device__ __forceinline__ float fast_exp2(float x) {
    float y; asm("ex2.approx.f32 %0, %1;" : "=f"(y) : "f"(x)); return y;
}
__device__ __forceinline__ uint32_t pack_bf16x2(float lo, float hi) {
    uint32_t r;
    asm("cvt.rn.satfinite.bf16x2.f32 %0, %1, %2;" : "=r"(r) : "f"(hi), "f"(lo));
    return r;
}
__device__ __forceinline__ void mma_bf16(float* d, const uint32_t* a,
                                         uint32_t b0, uint32_t b1) {
    asm volatile(
        "mma.sync.aligned.m16n8k16.row.col.f32.bf16.bf16.f32 "
        "{%0,%1,%2,%3}, {%4,%5,%6,%7}, {%8,%9}, {%0,%1,%2,%3};\n"
        : "+f"(d[0]), "+f"(d[1]), "+f"(d[2]), "+f"(d[3])
        : "r"(a[0]), "r"(a[1]), "r"(a[2]), "r"(a[3]), "r"(b0), "r"(b1));
}

// =====================================================================
// Weight fp32 -> bf16 conversion (wq, wk, wv)
// =====================================================================
__global__ void wconv_kernel(const float* __restrict__ wq,
                             const float* __restrict__ wk,
                             const float* __restrict__ wv)
{
    const int i = blockIdx.x * 256 + threadIdx.x;
    g_wqb[i] = __float2bfloat16_rn(wq[i]);
    g_wkb[i] = __float2bfloat16_rn(wk[i]);
    g_wvb[i] = __float2bfloat16_rn(wv[i]);
}

// =====================================================================
// GroupNorm: stats coalesced, normalize pass writes bf16 [b][n][c]
// =====================================================================
__global__ void gn_kernel(const float* __restrict__ x,
                          const float* __restrict__ cond,
                          const float* __restrict__ gqw, const float* __restrict__ gqb,
                          const float* __restrict__ gkw, const float* __restrict__ gkb)
{
    const int kv = blockIdx.y;
    const float* in  = kv ? cond : x;
    __nv_bfloat16* outb = kv ? g_kvnb : g_xnb;
    const float* gw  = kv ? gkw : gqw;
    const float* gb  = kv ? gkb : gqb;

    const int b = blockIdx.x / GROUPS;
    const int g = blockIdx.x % GROUPS;
    const size_t base_off = ((size_t)b*CH + (size_t)g*CPG) * HWN;
    const float4* in4 = (const float4*)(in + base_off);

    float s = 0.f, ss = 0.f;
    for (int i = threadIdx.x; i < (CPG*HWN)/4; i += 256) {
        float4 v = in4[i];
        s  += v.x + v.y + v.z + v.w;
        ss += v.x*v.x + v.y*v.y + v.z*v.z + v.w*v.w;
    }
    #pragma unroll
    for (int off = 16; off; off >>= 1) {
        s  += __shfl_xor_sync(0xffffffffu, s,  off);
        ss += __shfl_xor_sync(0xffffffffu, ss, off);
    }
    __shared__ float sm_s[8], sm_ss[8];
    if ((threadIdx.x & 31) == 0) { sm_s[threadIdx.x>>5] = s; sm_ss[threadIdx.x>>5] = ss; }
    __syncthreads();
    s = 0.f; ss = 0.f;
    #pragma unroll
    for (int w = 0; w < 8; w++) { s += sm_s[w]; ss += sm_ss[w]; }

    const float inv_n = 1.f / (float)(CPG*HWN);
    const float mean  = s * inv_n;
    const float var   = ss * inv_n - mean*mean;
    const float rstd  = rsqrtf(var + EPSV);

    float gwv[CPG], gbv[CPG];
    #pragma unroll
    for (int c = 0; c < CPG; c++) {
        gwv[c] = gw[g*CPG + c] * rstd;
        gbv[c] = gb[g*CPG + c] - mean * gwv[c];
    }

    const float* inp = in + base_off;
    for (int px = threadIdx.x; px < HWN; px += 256) {
        uint32_t p[4];
        #pragma unroll
        for (int c2 = 0; c2 < 4; c2++) {
            float v0 = inp[(size_t)(2*c2  )*HWN + px] * gwv[2*c2  ] + gbv[2*c2  ];
            float v1 = inp[(size_t)(2*c2+1)*HWN + px] * gwv[2*c2+1] + gbv[2*c2+1];
            p[c2] = pack_bf16x2(v0, v1);
        }
        *(uint4*)&outb[((size_t)b*HWN + px)*CH + g*CPG] =
            make_uint4(p[0], p[1], p[2], p[3]);
    }
}

// =====================================================================
// bf16 mma.sync GEMM for q/k/v projections.
// Y[ch][px] = sum_c W[ch][c] X[px][c];  M=256, N=4096, K=256 per batch.
// Block tile 128ch x 128px, 8 warps (wm 0..1 x wn 0..3), warp 64x32.
// mode: 1=q->[b][h][n][d]*QSCALE  2=k->[b][h][n][d]  3=v->[b][c][n]
// =====================================================================
#define WT_STR 72
#define CS_STR 136

__global__ void __launch_bounds__(256, 2) gemm_bf16(
    const __nv_bfloat16* __restrict__ Wb,
    const __nv_bfloat16* __restrict__ Xb,
    const float* __restrict__ bias,
    __nv_bfloat16* __restrict__ outb,
    int mode)
{
    __shared__ char buf[36864];
    __nv_bfloat16* Wts = (__nv_bfloat16*)buf;     // [128 ch][WT_STR]
    __nv_bfloat16* Xs  = Wts + 128*WT_STR;        // [128 px][WT_STR]
    __nv_bfloat16* Cs  = (__nv_bfloat16*)buf;     // [128 px][CS_STR] (epilogue)

    const int b  = blockIdx.z;
    const int m0 = blockIdx.y * 128;
    const int n0 = blockIdx.x * 128;

    const int t = threadIdx.x;
    const int lane = t & 31, warp = t >> 5;
    const int g = lane >> 2, qt = lane & 3;
    const int wm = warp >> 2, wn = warp & 3;

    const int srow = t >> 3, sseg = (t & 7) * 8;   // staging: 8 uint4-rows/row

    float acc[4][4][4];
    #pragma unroll
    for (int i = 0; i < 4; i++)
        #pragma unroll
        for (int j = 0; j < 4; j++)
            #pragma unroll
            for (int l = 0; l < 4; l++) acc[i][j][l] = 0.f;

    uint4 wreg[4], xreg[4];
    #pragma unroll
    for (int it = 0; it < 4; it++) {
        int row = srow + it*32;
        wreg[it] = *(const uint4*)&Wb[(size_t)(m0+row)*CH + sseg];
        xreg[it] = *(const uint4*)&Xb[((size_t)b*HWN + n0+row)*CH + sseg];
    }

    for (int c = 0; c < 4; c++) {
        if (c) __syncthreads();
        #pragma unroll
        for (int it = 0; it < 4; it++) {
            int row = srow + it*32;
            *(uint4*)&Wts[row*WT_STR + sseg] = wreg[it];
            *(uint4*)&Xs [row*WT_STR + sseg] = xreg[it];
        }
        __syncthreads();
        if (c + 1 < 4) {
            const int k0 = (c+1)*64;
            #pragma unroll
            for (int it = 0; it < 4; it++) {
                int row = srow + it*32;
                wreg[it] = *(const uint4*)&Wb[(size_t)(m0+row)*CH + k0 + sseg];
                xreg[it] = *(const uint4*)&Xb[((size_t)b*HWN + n0+row)*CH + k0 + sseg];
            }
        }
        #pragma unroll
        for (int kc = 0; kc < 4; kc++) {
            uint32_t a[4][4], b0[4], b1[4];
            #pragma unroll
            for (int mf = 0; mf < 4; mf++) {
                const __nv_bfloat16* wr = Wts + (wm*64 + mf*16 + g)*WT_STR + kc*16 + 2*qt;
                a[mf][0] = *(const uint32_t*)wr;
                a[mf][1] = *(const uint32_t*)(wr + 8*WT_STR);
                a[mf][2] = *(const uint32_t*)(wr + 8);
                a[mf][3] = *(const uint32_t*)(wr + 8*WT_STR + 8);
            }
            #pragma unroll
            for (int nf = 0; nf < 4; nf++) {
                const __nv_bfloat16* xr = Xs + (wn*32 + nf*8 + g)*WT_STR + kc*16 + 2*qt;
                b0[nf] = *(const uint32_t*)xr;
                b1[nf] = *(const uint32_t*)(xr + 8);
            }
            #pragma unroll
            for (int mf = 0; mf < 4; mf++)
                #pragma unroll
                for (int nf = 0; nf < 4; nf++)
                    mma_bf16(acc[mf][nf], a[mf], b0[nf], b1[nf]);
        }
    }

    if (mode == 3) {
        // V: direct [b][c][n] bf16x2 stores
        #pragma unroll
        for (int mf = 0; mf < 4; mf++) {
            const int ch = m0 + wm*64 + mf*16 + g;
            const float bb0 = bias[ch], bb1 = bias[ch + 8];
            #pragma unroll
            for (int nf = 0; nf < 4; nf++) {
                const int px = n0 + wn*32 + nf*8 + 2*qt;
                *(uint32_t*)&outb[((size_t)b*CH + ch)*HWN + px] =
                    pack_bf16x2(acc[mf][nf][0] + bb0, acc[mf][nf][1] + bb0);
                *(uint32_t*)&outb[((size_t)b*CH + ch + 8)*HWN + px] =
                    pack_bf16x2(acc[mf][nf][2] + bb1, acc[mf][nf][3] + bb1);
            }
        }
    } else {
        // Q/K: stage to SMEM [px][ch], then coalesced [b][h][n][d]
        const float sc = (mode == 1) ? QSCALE : 1.0f;
        __syncthreads();
        #pragma unroll
        for (int mf = 0; mf < 4; mf++) {
            const int chl = wm*64 + mf*16 + g;
            const float bb0 = bias[m0 + chl], bb1 = bias[m0 + chl + 8];
            #pragma unroll
            for (int nf = 0; nf < 4; nf++) {
                const int pxl = wn*32 + nf*8 + 2*qt;
                Cs[pxl*CS_STR + chl]       = __float2bfloat16_rn((acc[mf][nf][0] + bb0) * sc);
                Cs[(pxl+1)*CS_STR + chl]   = __float2bfloat16_rn((acc[mf][nf][1] + bb0) * sc);
                Cs[pxl*CS_STR + chl+8]     = __float2bfloat16_rn((acc[mf][nf][2] + bb1) * sc);
                Cs[(pxl+1)*CS_STR + chl+8] = __float2bfloat16_rn((acc[mf][nf][3] + bb1) * sc);
            }
        }
        __syncthreads();
        #pragma unroll
        for (int it = 0; it < 8; it++) {
            int i = t + it*256;
            int px = i >> 4, seg = i & 15;
            uint4 v = *(const uint4*)&Cs[px*CS_STR + seg*8];
            const int h = (m0 >> 6) + (seg >> 3);
            const int d = (seg & 7) * 8;
            *(uint4*)&outb[((size_t)(b*NHEADS + h)*HWN + n0 + px)*HD + d] = v;
        }
    }
}

// =====================================================================
// fp32 SIMT GEMM for the output projection (+ residual)
// =====================================================================
__global__ void gemm_kernel(const float* __restrict__ W,
                            const float* __restrict__ X,
                            const float* __restrict__ bias,
                            const float* __restrict__ res,
                            float* __restrict__ outf)
{
    const int b  = blockIdx.z;
    const int m0 = blockIdx.y * 64;
    const int n0 = blockIdx.x * 64;
    const float* Xb = X + (size_t)b*CH*HWN;

    __shared__ float Wts2[16][68];
    __shared__ float Xs2 [16][64];

    const int t  = threadIdx.x;
    const int tx = t & 15, ty = t >> 4;
    const int wr = t >> 2, wc4 = (t & 3) * 4;
    const int xr = t >> 4, xc4 = (t & 15) * 4;

    float acc[4][4] = {};

    for (int k0 = 0; k0 < CH; k0 += 16) {
        float4 wv = *(const float4*)&W[(size_t)(m0+wr)*CH + k0 + wc4];
        Wts2[wc4+0][wr] = wv.x;
        Wts2[wc4+1][wr] = wv.y;
        Wts2[wc4+2][wr] = wv.z;
        Wts2[wc4+3][wr] = wv.w;
        *(float4*)&Xs2[xr][xc4] =
            *(const float4*)&Xb[(size_t)(k0+xr)*HWN + n0 + xc4];
        __syncthreads();
        #pragma unroll
        for (int kk = 0; kk < 16; kk++) {
            float4 a  = *(const float4*)&Wts2[kk][ty*4];
            float4 bb = *(const float4*)&Xs2[kk][tx*4];
            float av[4] = {a.x, a.y, a.z, a.w};
            float bv2[4] = {bb.x, bb.y, bb.z, bb.w};
            #pragma unroll
            for (int i = 0; i < 4; i++)
                #pragma unroll
                for (int j = 0; j < 4; j++)
                    acc[i][j] = fmaf(av[i], bv2[j], acc[i][j]);
        }
        __syncthreads();
    }

    #pragma unroll
    for (int i = 0; i < 4; i++) {
        const int row = m0 + ty*4 + i;
        const float bv = bias[row];
        const size_t off = (size_t)b*CH*HWN + (size_t)row*HWN + n0 + tx*4;
        float4 o;
        o.x = acc[i][0] + bv; o.y = acc[i][1] + bv;
        o.z = acc[i][2] + bv; o.w = acc[i][3] + bv;
        float4 r = *(const float4*)&res[off];
        o.x += r.x; o.y += r.y; o.z += r.z; o.w += r.w;
        *(float4*)&outf[off] = o;
    }
}

// =====================================================================
// bf16 mma.sync flash attention (no online max: logits bounded)
// =====================================================================
#define KS_STR 72
#define PS_STR 72
#define OW_STR 65

__global__ void __launch_bounds__(256, 2) attn_mma_bf16()
{
    __shared__ char smbuf[36864];
    __nv_bfloat16* Ks = (__nv_bfloat16*)smbuf;   // [64 key][KS_STR d]
    __nv_bfloat16* Vs = Ks + 64*KS_STR;          // [64 d][KS_STR key]
    __nv_bfloat16* Ps = Vs + 64*KS_STR;          // 8 warps x [16 n][PS_STR m]
    float*         Ow = (float*)smbuf;           // [128 n][OW_STR d] (reused)

    const int bh = blockIdx.y;
    const int b = bh >> 2, h = bh & 3;
    const int n0 = blockIdx.x * 128;
    const __nv_bfloat16* Qg = g_qb + (size_t)(b*NHEADS + h) * HWN * HD;
    const __nv_bfloat16* Kg = g_kb + (size_t)(b*NHEADS + h) * HWN * HD;
    const __nv_bfloat16* Vg = g_vb + ((size_t)b*CH + (size_t)h*HD) * HWN;

    const int t = threadIdx.x;
    const int lane = t & 31, warp = t >> 5;
    const int g = lane >> 2, tid = lane & 3;
    const int nb = warp * 16;

    uint32_t qa[4][4];
    {
        const __nv_bfloat16* q0 = Qg + (size_t)(n0 + nb + g) * HD;
        const __nv_bfloat16* q1 = Qg + (size_t)(n0 + nb + g + 8) * HD;
        #pragma unroll
        for (int kc = 0; kc < 4; kc++) {
            qa[kc][0] = *(const uint32_t*)(q0 + kc*16 + 2*tid);
            qa[kc][1] = *(const uint32_t*)(q1 + kc*16 + 2*tid);
            qa[kc][2] = *(const uint32_t*)(q0 + kc*16 + 2*tid + 8);
            qa[kc][3] = *(const uint32_t*)(q1 + kc*16 + 2*tid + 8);
        }
    }

    float oa[8][4];
    #pragma unroll
    for (int i = 0; i < 8; i++)
        #pragma unroll
        for (int j = 0; j < 4; j++) oa[i][j] = 0.f;
    float ls0 = 0.f, ls1 = 0.f;

    __nv_bfloat16* Pw = Ps + warp*16*PS_STR;

    for (int j0 = 0; j0 < HWN; j0 += 64) {
        __syncthreads();
        #pragma unroll
        for (int it = 0; it < 2; it++) {
            int i = t + it*256;
            int row = i >> 3, seg = (i & 7) * 8;
            *(uint4*)(Ks + row*KS_STR + seg) =
                *(const uint4*)(Kg + (size_t)(j0 + row)*HD + seg);
            *(uint4*)(Vs + row*KS_STR + seg) =
                *(const uint4*)(Vg + (size_t)row*HWN + j0 + seg);
        }
        __syncthreads();

        float sa[8][4];
        #pragma unroll
        for (int mt = 0; mt < 8; mt++)
            #pragma unroll
            for (int j = 0; j < 4; j++) sa[mt][j] = 0.f;

        #pragma unroll
        for (int kc = 0; kc < 4; kc++) {
            #pragma unroll
            for (int mt = 0; mt < 8; mt++) {
                const __nv_bfloat16* kr = Ks + (mt*8 + g)*KS_STR + kc*16 + 2*tid;
                uint32_t b0 = *(const uint32_t*)kr;
                uint32_t b1 = *(const uint32_t*)(kr + 8);
                mma_bf16(sa[mt], qa[kc], b0, b1);
            }
        }

        #pragma unroll
        for (int mt = 0; mt < 8; mt++) {
            float e0 = fast_exp2(sa[mt][0]);
            float e1 = fast_exp2(sa[mt][1]);
            float e2 = fast_exp2(sa[mt][2]);
            float e3 = fast_exp2(sa[mt][3]);
            ls0 += e0 + e1;
            ls1 += e2 + e3;
            *(uint32_t*)(Pw + g*PS_STR + mt*8 + 2*tid)     = pack_bf16x2(e0, e1);
            *(uint32_t*)(Pw + (g+8)*PS_STR + mt*8 + 2*tid) = pack_bf16x2(e2, e3);
        }
        __syncwarp();

        #pragma unroll
        for (int kc = 0; kc < 4; kc++) {
            uint32_t pa[4];
            pa[0] = *(const uint32_t*)(Pw + g*PS_STR + kc*16 + 2*tid);
            pa[1] = *(const uint32_t*)(Pw + (g+8)*PS_STR + kc*16 + 2*tid);
            pa[2] = *(const uint32_t*)(Pw + g*PS_STR + kc*16 + 2*tid + 8);
            pa[3] = *(const uint32_t*)(Pw + (g+8)*PS_STR + kc*16 + 2*tid + 8);
            #pragma unroll
            for (int dt = 0; dt < 8; dt++) {
                const __nv_bfloat16* vr = Vs + (dt*8 + g)*KS_STR + kc*16 + 2*tid;
                uint32_t b0 = *(const uint32_t*)vr;
                uint32_t b1 = *(const uint32_t*)(vr + 8);
                mma_bf16(oa[dt], pa, b0, b1);
            }
        }
    }

    ls0 += __shfl_xor_sync(0xffffffffu, ls0, 1);
    ls0 += __shfl_xor_sync(0xffffffffu, ls0, 2);
    ls1 += __shfl_xor_sync(0xffffffffu, ls1, 1);
    ls1 += __shfl_xor_sync(0xffffffffu, ls1, 2);
    const float li0 = 1.f / ls0;
    const float li1 = 1.f / ls1;

    __syncthreads();
    #pragma unroll
    for (int dt = 0; dt < 8; dt++) {
        Ow[(nb+g)*OW_STR + dt*8 + 2*tid]       = oa[dt][0]*li0;
        Ow[(nb+g)*OW_STR + dt*8 + 2*tid + 1]   = oa[dt][1]*li0;
        Ow[(nb+g+8)*OW_STR + dt*8 + 2*tid]     = oa[dt][2]*li1;
        Ow[(nb+g+8)*OW_STR + dt*8 + 2*tid + 1] = oa[dt][3]*li1;
    }
    __syncthreads();

    float* Og = g_ao + ((size_t)b*CH + (size_t)h*HD) * HWN;
    for (int i = t; i < 64*128; i += 256) {
        int d = i >> 7, n = i & 127;
        Og[(size_t)d*HWN + n0 + n] = Ow[n*OW_STR + d];
    }
}

// =====================================================================
extern "C" void kernel_launch(void* const* d_in, const int* in_sizes, int n_in,
                              void* d_out, int out_size)
{
    const float* x    = (const float*)d_in[0];
    const float* cond = (const float*)d_in[1];
    const float* gqw  = (const float*)d_in[2];
    const float* gqb  = (const float*)d_in[3];
    const float* gkw  = (const float*)d_in[4];
    const float* gkb  = (const float*)d_in[5];
    const float* wq   = (const float*)d_in[6];
    const float* bq   = (const float*)d_in[7];
    const float* wk   = (const float*)d_in[8];
    const float* bk   = (const float*)d_in[9];
    const float* wv   = (const float*)d_in[10];
    const float* bv   = (const float*)d_in[11];
    const float* wo   = (const float*)d_in[12];
    const float* bo   = (const float*)d_in[13];
    float* out = (float*)d_out;

    float *p_ao;
    __nv_bfloat16 *p_xnb, *p_kvnb, *p_qb, *p_kb, *p_vb, *p_wqb, *p_wkb, *p_wvb;
    cudaGetSymbolAddress((void**)&p_ao,   g_ao);
    cudaGetSymbolAddress((void**)&p_xnb,  g_xnb);
    cudaGetSymbolAddress((void**)&p_kvnb, g_kvnb);
    cudaGetSymbolAddress((void**)&p_qb,   g_qb);
    cudaGetSymbolAddress((void**)&p_kb,   g_kb);
    cudaGetSymbolAddress((void**)&p_vb,   g_vb);
    cudaGetSymbolAddress((void**)&p_wqb,  g_wqb);
    cudaGetSymbolAddress((void**)&p_wkb,  g_wkb);
    cudaGetSymbolAddress((void**)&p_wvb,  g_wvb);

    wconv_kernel<<<CH*CH/256, 256>>>(wq, wk, wv);
    gn_kernel<<<dim3(BATCH*GROUPS, 2), 256>>>(x, cond, gqw, gqb, gkw, gkb);

    dim3 bgrid(HWN/128, CH/128, BATCH);
    gemm_bf16<<<bgrid, 256>>>(p_wqb, p_xnb,  bq, p_qb, 1);
    gemm_bf16<<<bgrid, 256>>>(p_wkb, p_kvnb, bk, p_kb, 2);
    gemm_bf16<<<bgrid, 256>>>(p_wvb, p_kvnb, bv, p_vb, 3);

    attn_mma_bf16<<<dim3(HWN/128, BATCH*NHEADS), 256>>>();

    dim3 ggrid(HWN/64, CH/64, BATCH);
    gemm_kernel<<<ggrid, 256>>>(wo, p_ao, bo, x, out);
}

// round 7
// speedup vs baseline: 7.4768x; 1.3666x over previous
#include <cuda_runtime.h>
#include <cuda_bf16.h>
#include <math.h>
#include <stdint.h>

#define BATCH 4
#define CH    256
#define HWN   4096
#define GROUPS 32
#define CPG   8
#define NHEADS 4
#define HD    64
#define EPSV  1e-5f
#define QSCALE 0.18033688011112042f   // 0.125 * log2(e)

// ---- scratch (__device__ globals; allocation-free) ----
__device__ __nv_bfloat16 g_xnb [BATCH*HWN*CH];  // GN(x), [b][n][c]
__device__ __nv_bfloat16 g_kvnb[BATCH*HWN*CH];  // GN(cond), [b][n][c]
__device__ __nv_bfloat16 g_qb[BATCH*CH*HWN];    // [b][h][n][d], pre-scaled
__device__ __nv_bfloat16 g_kb[BATCH*CH*HWN];    // [b][h][n][d]
__device__ __nv_bfloat16 g_vb[BATCH*CH*HWN];    // [b][c][n]
__device__ __nv_bfloat16 g_aob[BATCH*HWN*CH];   // attn out, [b][n][c]
__device__ __nv_bfloat16 g_wqb[CH*CH], g_wkb[CH*CH], g_wvb[CH*CH], g_wob[CH*CH];

__device__ __forceinline__ float fast_exp2(float x) {
    float y; asm("ex2.approx.f32 %0, %1;" : "=f"(y) : "f"(x)); return y;
}
__device__ __forceinline__ uint32_t pack_bf16x2(float lo, float hi) {
    uint32_t r;
    asm("cvt.rn.satfinite.bf16x2.f32 %0, %1, %2;" : "=r"(r) : "f"(hi), "f"(lo));
    return r;
}
__device__ __forceinline__ void mma_bf16(float* d, const uint32_t* a,
                                         uint32_t b0, uint32_t b1) {
    asm volatile(
        "mma.sync.aligned.m16n8k16.row.col.f32.bf16.bf16.f32 "
        "{%0,%1,%2,%3}, {%4,%5,%6,%7}, {%8,%9}, {%0,%1,%2,%3};\n"
        : "+f"(d[0]), "+f"(d[1]), "+f"(d[2]), "+f"(d[3])
        : "r"(a[0]), "r"(a[1]), "r"(a[2]), "r"(a[3]), "r"(b0), "r"(b1));
}
__device__ __forceinline__ void ldsm_x4(uint32_t& r0, uint32_t& r1,
                                        uint32_t& r2, uint32_t& r3, uint32_t sa) {
    asm volatile("ldmatrix.sync.aligned.m8n8.x4.shared.b16 {%0,%1,%2,%3}, [%4];"
                 : "=r"(r0), "=r"(r1), "=r"(r2), "=r"(r3) : "r"(sa));
}
__device__ __forceinline__ uint32_t smem_u32(const void* p) {
    return (uint32_t)__cvta_generic_to_shared(p);
}

// =====================================================================
// Weight fp32 -> bf16
// =====================================================================
__global__ void wconv_kernel(const float* __restrict__ wq,
                             const float* __restrict__ wk,
                             const float* __restrict__ wv,
                             const float* __restrict__ wo)
{
    const int i = blockIdx.x * 256 + threadIdx.x;
    g_wqb[i] = __float2bfloat16_rn(wq[i]);
    g_wkb[i] = __float2bfloat16_rn(wk[i]);
    g_wvb[i] = __float2bfloat16_rn(wv[i]);
    g_wob[i] = __float2bfloat16_rn(wo[i]);
}

// =====================================================================
// GroupNorm -> bf16 [b][n][c]
// =====================================================================
__global__ void gn_kernel(const float* __restrict__ x,
                          const float* __restrict__ cond,
                          const float* __restrict__ gqw, const float* __restrict__ gqb,
                          const float* __restrict__ gkw, const float* __restrict__ gkb)
{
    const int kv = blockIdx.y;
    const float* in  = kv ? cond : x;
    __nv_bfloat16* outb = kv ? g_kvnb : g_xnb;
    const float* gw  = kv ? gkw : gqw;
    const float* gb  = kv ? gkb : gqb;

    const int b = blockIdx.x / GROUPS;
    const int g = blockIdx.x % GROUPS;
    const size_t base_off = ((size_t)b*CH + (size_t)g*CPG) * HWN;
    const float4* in4 = (const float4*)(in + base_off);

    float s = 0.f, ss = 0.f;
    for (int i = threadIdx.x; i < (CPG*HWN)/4; i += 256) {
        float4 v = in4[i];
        s  += v.x + v.y + v.z + v.w;
        ss += v.x*v.x + v.y*v.y + v.z*v.z + v.w*v.w;
    }
    #pragma unroll
    for (int off = 16; off; off >>= 1) {
        s  += __shfl_xor_sync(0xffffffffu, s,  off);
        ss += __shfl_xor_sync(0xffffffffu, ss, off);
    }
    __shared__ float sm_s[8], sm_ss[8];
    if ((threadIdx.x & 31) == 0) { sm_s[threadIdx.x>>5] = s; sm_ss[threadIdx.x>>5] = ss; }
    __syncthreads();
    s = 0.f; ss = 0.f;
    #pragma unroll
    for (int w = 0; w < 8; w++) { s += sm_s[w]; ss += sm_ss[w]; }

    const float inv_n = 1.f / (float)(CPG*HWN);
    const float mean  = s * inv_n;
    const float var   = ss * inv_n - mean*mean;
    const float rstd  = rsqrtf(var + EPSV);

    float gwv[CPG], gbv[CPG];
    #pragma unroll
    for (int c = 0; c < CPG; c++) {
        gwv[c] = gw[g*CPG + c] * rstd;
        gbv[c] = gb[g*CPG + c] - mean * gwv[c];
    }

    const float* inp = in + base_off;
    for (int px = threadIdx.x; px < HWN; px += 256) {
        uint32_t p[4];
        #pragma unroll
        for (int c2 = 0; c2 < 4; c2++) {
            float v0 = inp[(size_t)(2*c2  )*HWN + px] * gwv[2*c2  ] + gbv[2*c2  ];
            float v1 = inp[(size_t)(2*c2+1)*HWN + px] * gwv[2*c2+1] + gbv[2*c2+1];
            p[c2] = pack_bf16x2(v0, v1);
        }
        *(uint4*)&outb[((size_t)b*HWN + px)*CH + g*CPG] =
            make_uint4(p[0], p[1], p[2], p[3]);
    }
}

// =====================================================================
// bf16 mma GEMM: Y[ch][px] = sum_c W[ch][c] X[px][c]
// Block 128ch x 128px; 8 warps 64x32.
// mode: 0=fp32 out [b][c][n] + bias + residual
//       1=q bf16 [b][h][n][d]*QSCALE   2=k bf16 [b][h][n][d]
//       3=v bf16 [b][c][n]
// =====================================================================
#define WT_STR 72
#define CS_STR 136

__global__ void __launch_bounds__(256, 2) gemm_bf16(
    const __nv_bfloat16* __restrict__ Wb,
    const __nv_bfloat16* __restrict__ Xb,
    const float* __restrict__ bias,
    __nv_bfloat16* __restrict__ outb,
    int mode,
    const float* __restrict__ res,
    float* __restrict__ outf)
{
    __shared__ char buf[36864];
    __nv_bfloat16* Wts = (__nv_bfloat16*)buf;     // [128 ch][WT_STR]
    __nv_bfloat16* Xs  = Wts + 128*WT_STR;        // [128 px][WT_STR]
    __nv_bfloat16* Cs  = (__nv_bfloat16*)buf;     // epilogue restage (q/k)

    const int b  = blockIdx.z;
    const int m0 = blockIdx.y * 128;
    const int n0 = blockIdx.x * 128;

    const int t = threadIdx.x;
    const int lane = t & 31, warp = t >> 5;
    const int g = lane >> 2, qt = lane & 3;
    const int wm = warp >> 2, wn = warp & 3;

    const int srow = t >> 3, sseg = (t & 7) * 8;

    float acc[4][4][4];
    #pragma unroll
    for (int i = 0; i < 4; i++)
        #pragma unroll
        for (int j = 0; j < 4; j++)
            #pragma unroll
            for (int l = 0; l < 4; l++) acc[i][j][l] = 0.f;

    uint4 wreg[4], xreg[4];
    #pragma unroll
    for (int it = 0; it < 4; it++) {
        int row = srow + it*32;
        wreg[it] = *(const uint4*)&Wb[(size_t)(m0+row)*CH + sseg];
        xreg[it] = *(const uint4*)&Xb[((size_t)b*HWN + n0+row)*CH + sseg];
    }

    for (int c = 0; c < 4; c++) {
        if (c) __syncthreads();
        #pragma unroll
        for (int it = 0; it < 4; it++) {
            int row = srow + it*32;
            *(uint4*)&Wts[row*WT_STR + sseg] = wreg[it];
            *(uint4*)&Xs [row*WT_STR + sseg] = xreg[it];
        }
        __syncthreads();
        if (c + 1 < 4) {
            const int k0 = (c+1)*64;
            #pragma unroll
            for (int it = 0; it < 4; it++) {
                int row = srow + it*32;
                wreg[it] = *(const uint4*)&Wb[(size_t)(m0+row)*CH + k0 + sseg];
                xreg[it] = *(const uint4*)&Xb[((size_t)b*HWN + n0+row)*CH + k0 + sseg];
            }
        }
        #pragma unroll
        for (int kc = 0; kc < 4; kc++) {
            uint32_t a[4][4], b0[4], b1[4];
            #pragma unroll
            for (int mf = 0; mf < 4; mf++) {
                const __nv_bfloat16* wr = Wts + (wm*64 + mf*16 + g)*WT_STR + kc*16 + 2*qt;
                a[mf][0] = *(const uint32_t*)wr;
                a[mf][1] = *(const uint32_t*)(wr + 8*WT_STR);
                a[mf][2] = *(const uint32_t*)(wr + 8);
                a[mf][3] = *(const uint32_t*)(wr + 8*WT_STR + 8);
            }
            #pragma unroll
            for (int nf = 0; nf < 4; nf++) {
                const __nv_bfloat16* xr = Xs + (wn*32 + nf*8 + g)*WT_STR + kc*16 + 2*qt;
                b0[nf] = *(const uint32_t*)xr;
                b1[nf] = *(const uint32_t*)(xr + 8);
            }
            #pragma unroll
            for (int mf = 0; mf < 4; mf++)
                #pragma unroll
                for (int nf = 0; nf < 4; nf++)
                    mma_bf16(acc[mf][nf], a[mf], b0[nf], b1[nf]);
        }
    }

    if (mode == 0) {
        // fp32 [b][c][n] + bias + residual
        #pragma unroll
        for (int mf = 0; mf < 4; mf++) {
            const int ch = m0 + wm*64 + mf*16 + g;
            const float bb0 = bias[ch], bb1 = bias[ch + 8];
            #pragma unroll
            for (int nf = 0; nf < 4; nf++) {
                const int px = n0 + wn*32 + nf*8 + 2*qt;
                const size_t o0 = ((size_t)b*CH + ch)*HWN + px;
                const size_t o1 = ((size_t)b*CH + ch + 8)*HWN + px;
                float2 r0 = *(const float2*)&res[o0];
                float2 r1 = *(const float2*)&res[o1];
                float2 v0 = make_float2(acc[mf][nf][0] + bb0 + r0.x,
                                        acc[mf][nf][1] + bb0 + r0.y);
                float2 v1 = make_float2(acc[mf][nf][2] + bb1 + r1.x,
                                        acc[mf][nf][3] + bb1 + r1.y);
                *(float2*)&outf[o0] = v0;
                *(float2*)&outf[o1] = v1;
            }
        }
    } else if (mode == 3) {
        #pragma unroll
        for (int mf = 0; mf < 4; mf++) {
            const int ch = m0 + wm*64 + mf*16 + g;
            const float bb0 = bias[ch], bb1 = bias[ch + 8];
            #pragma unroll
            for (int nf = 0; nf < 4; nf++) {
                const int px = n0 + wn*32 + nf*8 + 2*qt;
                *(uint32_t*)&outb[((size_t)b*CH + ch)*HWN + px] =
                    pack_bf16x2(acc[mf][nf][0] + bb0, acc[mf][nf][1] + bb0);
                *(uint32_t*)&outb[((size_t)b*CH + ch + 8)*HWN + px] =
                    pack_bf16x2(acc[mf][nf][2] + bb1, acc[mf][nf][3] + bb1);
            }
        }
    } else {
        // Q/K: stage to SMEM [px][ch] then coalesced [b][h][n][d]
        const float sc = (mode == 1) ? QSCALE : 1.0f;
        __syncthreads();
        #pragma unroll
        for (int mf = 0; mf < 4; mf++) {
            const int chl = wm*64 + mf*16 + g;
            const float bb0 = bias[m0 + chl], bb1 = bias[m0 + chl + 8];
            #pragma unroll
            for (int nf = 0; nf < 4; nf++) {
                const int pxl = wn*32 + nf*8 + 2*qt;
                Cs[pxl*CS_STR + chl]       = __float2bfloat16_rn((acc[mf][nf][0] + bb0) * sc);
                Cs[(pxl+1)*CS_STR + chl]   = __float2bfloat16_rn((acc[mf][nf][1] + bb0) * sc);
                Cs[pxl*CS_STR + chl+8]     = __float2bfloat16_rn((acc[mf][nf][2] + bb1) * sc);
                Cs[(pxl+1)*CS_STR + chl+8] = __float2bfloat16_rn((acc[mf][nf][3] + bb1) * sc);
            }
        }
        __syncthreads();
        #pragma unroll
        for (int it = 0; it < 8; it++) {
            int i = t + it*256;
            int px = i >> 4, seg = i & 15;
            uint4 v = *(const uint4*)&Cs[px*CS_STR + seg*8];
            const int h = (m0 >> 6) + (seg >> 3);
            const int d = (seg & 7) * 8;
            *(uint4*)&outb[((size_t)(b*NHEADS + h)*HWN + n0 + px)*HD + d] = v;
        }
    }
}

// =====================================================================
// bf16 mma flash attention. P kept entirely in registers
// (S C-frag == PV A-frag layout); ldmatrix for K/V fragments.
// =====================================================================
#define KS_STR 72

__global__ void __launch_bounds__(256, 2) attn_mma_bf16()
{
    __shared__ __nv_bfloat16 Ks[64*KS_STR];   // [key][d]
    __shared__ __nv_bfloat16 Vs[64*KS_STR];   // [d][key]

    const int bh = blockIdx.y;
    const int b = bh >> 2, h = bh & 3;
    const int n0 = blockIdx.x * 128;
    const __nv_bfloat16* Qg = g_qb + (size_t)(b*NHEADS + h) * HWN * HD;
    const __nv_bfloat16* Kg = g_kb + (size_t)(b*NHEADS + h) * HWN * HD;
    const __nv_bfloat16* Vg = g_vb + ((size_t)b*CH + (size_t)h*HD) * HWN;

    const int t = threadIdx.x;
    const int lane = t & 31, warp = t >> 5;
    const int g = lane >> 2, tid = lane & 3;
    const int nb = warp * 16;

    // ldmatrix per-lane offset: row (lane&7), matrix (lane>>3) -> +8 elems
    const uint32_t lds_off = (uint32_t)(((lane & 7) * KS_STR + (lane >> 3) * 8) * 2);
    const uint32_t ks_base = smem_u32(Ks) + lds_off;
    const uint32_t vs_base = smem_u32(Vs) + lds_off;

    // staging indices: 2 uint4 per thread per tile
    const int srow0 = t >> 3,        sseg = (t & 7) * 8;
    const int srow1 = (t + 256) >> 3;

    // Q A-fragments (persist)
    uint32_t qa[4][4];
    {
        const __nv_bfloat16* q0 = Qg + (size_t)(n0 + nb + g) * HD;
        const __nv_bfloat16* q1 = Qg + (size_t)(n0 + nb + g + 8) * HD;
        #pragma unroll
        for (int kc = 0; kc < 4; kc++) {
            qa[kc][0] = *(const uint32_t*)(q0 + kc*16 + 2*tid);
            qa[kc][1] = *(const uint32_t*)(q1 + kc*16 + 2*tid);
            qa[kc][2] = *(const uint32_t*)(q0 + kc*16 + 2*tid + 8);
            qa[kc][3] = *(const uint32_t*)(q1 + kc*16 + 2*tid + 8);
        }
    }

    float oa[8][4];
    #pragma unroll
    for (int i = 0; i < 8; i++)
        #pragma unroll
        for (int j = 0; j < 4; j++) oa[i][j] = 0.f;
    float ls0 = 0.f, ls1 = 0.f;

    // prefetch tile 0
    uint4 kreg0 = *(const uint4*)(Kg + (size_t)srow0*HD + sseg);
    uint4 kreg1 = *(const uint4*)(Kg + (size_t)srow1*HD + sseg);
    uint4 vreg0 = *(const uint4*)(Vg + (size_t)srow0*HWN + sseg);
    uint4 vreg1 = *(const uint4*)(Vg + (size_t)srow1*HWN + sseg);

    for (int j0 = 0; j0 < HWN; j0 += 64) {
        __syncthreads();
        *(uint4*)(Ks + srow0*KS_STR + sseg) = kreg0;
        *(uint4*)(Ks + srow1*KS_STR + sseg) = kreg1;
        *(uint4*)(Vs + srow0*KS_STR + sseg) = vreg0;
        *(uint4*)(Vs + srow1*KS_STR + sseg) = vreg1;
        __syncthreads();

        if (j0 + 64 < HWN) {
            const int j1 = j0 + 64;
            kreg0 = *(const uint4*)(Kg + (size_t)(j1+srow0)*HD + sseg);
            kreg1 = *(const uint4*)(Kg + (size_t)(j1+srow1)*HD + sseg);
            vreg0 = *(const uint4*)(Vg + (size_t)srow0*HWN + j1 + sseg);
            vreg1 = *(const uint4*)(Vg + (size_t)srow1*HWN + j1 + sseg);
        }

        // ---- S = Q K^T ----
        float sa[8][4];
        #pragma unroll
        for (int mt = 0; mt < 8; mt++) {
            uint32_t kb[8];
            const uint32_t base = ks_base + (uint32_t)(mt * 8 * KS_STR * 2);
            ldsm_x4(kb[0], kb[1], kb[2], kb[3], base);
            ldsm_x4(kb[4], kb[5], kb[6], kb[7], base + 64);
            #pragma unroll
            for (int j = 0; j < 4; j++) sa[mt][j] = 0.f;
            #pragma unroll
            for (int kc = 0; kc < 4; kc++)
                mma_bf16(sa[mt], qa[kc], kb[2*kc], kb[2*kc+1]);
        }

        // ---- exp2 + pack P A-frags in registers ----
        uint32_t pe[4][4];
        #pragma unroll
        for (int kc = 0; kc < 4; kc++) {
            float e00 = fast_exp2(sa[2*kc][0]);
            float e01 = fast_exp2(sa[2*kc][1]);
            float e02 = fast_exp2(sa[2*kc][2]);
            float e03 = fast_exp2(sa[2*kc][3]);
            float e10 = fast_exp2(sa[2*kc+1][0]);
            float e11 = fast_exp2(sa[2*kc+1][1]);
            float e12 = fast_exp2(sa[2*kc+1][2]);
            float e13 = fast_exp2(sa[2*kc+1][3]);
            ls0 += e00 + e01 + e10 + e11;
            ls1 += e02 + e03 + e12 + e13;
            pe[kc][0] = pack_bf16x2(e00, e01);
            pe[kc][1] = pack_bf16x2(e02, e03);
            pe[kc][2] = pack_bf16x2(e10, e11);
            pe[kc][3] = pack_bf16x2(e12, e13);
        }

        // ---- O += P V^T ----
        #pragma unroll
        for (int dt = 0; dt < 8; dt++) {
            uint32_t vb[8];
            const uint32_t base = vs_base + (uint32_t)(dt * 8 * KS_STR * 2);
            ldsm_x4(vb[0], vb[1], vb[2], vb[3], base);
            ldsm_x4(vb[4], vb[5], vb[6], vb[7], base + 64);
            #pragma unroll
            for (int kc = 0; kc < 4; kc++)
                mma_bf16(oa[dt], pe[kc], vb[2*kc], vb[2*kc+1]);
        }
    }

    // ---- normalize + store bf16 [b][n][c] ----
    ls0 += __shfl_xor_sync(0xffffffffu, ls0, 1);
    ls0 += __shfl_xor_sync(0xffffffffu, ls0, 2);
    ls1 += __shfl_xor_sync(0xffffffffu, ls1, 1);
    ls1 += __shfl_xor_sync(0xffffffffu, ls1, 2);
    const float li0 = 1.f / ls0;
    const float li1 = 1.f / ls1;

    __nv_bfloat16* O0 = g_aob + ((size_t)b*HWN + n0 + nb + g)*CH + h*HD + 2*tid;
    __nv_bfloat16* O1 = O0 + 8*CH;
    #pragma unroll
    for (int dt = 0; dt < 8; dt++) {
        *(uint32_t*)(O0 + dt*8) = pack_bf16x2(oa[dt][0]*li0, oa[dt][1]*li0);
        *(uint32_t*)(O1 + dt*8) = pack_bf16x2(oa[dt][2]*li1, oa[dt][3]*li1);
    }
}

// =====================================================================
extern "C" void kernel_launch(void* const* d_in, const int* in_sizes, int n_in,
                              void* d_out, int out_size)
{
    const float* x    = (const float*)d_in[0];
    const float* cond = (const float*)d_in[1];
    const float* gqw  = (const float*)d_in[2];
    const float* gqb  = (const float*)d_in[3];
    const float* gkw  = (const float*)d_in[4];
    const float* gkb  = (const float*)d_in[5];
    const float* wq   = (const float*)d_in[6];
    const float* bq   = (const float*)d_in[7];
    const float* wk   = (const float*)d_in[8];
    const float* bk   = (const float*)d_in[9];
    const float* wv   = (const float*)d_in[10];
    const float* bv   = (const float*)d_in[11];
    const float* wo   = (const float*)d_in[12];
    const float* bo   = (const float*)d_in[13];
    float* out = (float*)d_out;

    __nv_bfloat16 *p_xnb, *p_kvnb, *p_qb, *p_kb, *p_vb, *p_aob;
    __nv_bfloat16 *p_wqb, *p_wkb, *p_wvb, *p_wob;
    cudaGetSymbolAddress((void**)&p_xnb,  g_xnb);
    cudaGetSymbolAddress((void**)&p_kvnb, g_kvnb);
    cudaGetSymbolAddress((void**)&p_qb,   g_qb);
    cudaGetSymbolAddress((void**)&p_kb,   g_kb);
    cudaGetSymbolAddress((void**)&p_vb,   g_vb);
    cudaGetSymbolAddress((void**)&p_aob,  g_aob);
    cudaGetSymbolAddress((void**)&p_wqb,  g_wqb);
    cudaGetSymbolAddress((void**)&p_wkb,  g_wkb);
    cudaGetSymbolAddress((void**)&p_wvb,  g_wvb);
    cudaGetSymbolAddress((void**)&p_wob,  g_wob);

    wconv_kernel<<<CH*CH/256, 256>>>(wq, wk, wv, wo);
    gn_kernel<<<dim3(BATCH*GROUPS, 2), 256>>>(x, cond, gqw, gqb, gkw, gkb);

    dim3 bgrid(HWN/128, CH/128, BATCH);
    gemm_bf16<<<bgrid, 256>>>(p_wqb, p_xnb,  bq, p_qb, 1, nullptr, nullptr);
    gemm_bf16<<<bgrid, 256>>>(p_wkb, p_kvnb, bk, p_kb, 2, nullptr, nullptr);
    gemm_bf16<<<bgrid, 256>>>(p_wvb, p_kvnb, bv, p_vb, 3, nullptr, nullptr);

    attn_mma_bf16<<<dim3(HWN/128, BATCH*NHEADS), 256>>>();

    gemm_bf16<<<bgrid, 256>>>(p_wob, p_aob, bo, nullptr, 0, x, out);
}